// round 7
// baseline (speedup 1.0000x reference)
#include <cuda_runtime.h>

#define N_NODES 100000
#define IN_DIM  512
#define OUT_DIM 16
#define N_EDGES 3200000

// Scratch (allocation-free rule: __device__ globals).
__device__ int   g_is64;                  // 1 if edge_index buffer is int64
__device__ int   g_cnt[N_NODES];          // in-degree (edges only, no self loop)
__device__ int   g_cur[N_NODES];          // scatter cursors
__device__ int   g_off[N_NODES];          // exclusive prefix of g_cnt
__device__ int   g_src32[N_EDGES];
__device__ int   g_dst32[N_EDGES];
__device__ int   g_sorted_src[N_EDGES];   // src ids grouped by dst
__device__ __align__(16) float g_feat[N_NODES * OUT_DIM]; // rsqrt(deg)*(x@W)

// ---------------------------------------------------------------------------
// K0: dtype detection. int64 node ids < 2^31 have zero high words -> odd
//     int32 positions all zero. int32 ids are random in [0,100000): odd
//     positions ~never zero. Reads only 1KB (in-bounds either way).
// ---------------------------------------------------------------------------
__global__ void detect_kernel(const int* __restrict__ ei32) {
    if (threadIdx.x == 0 && blockIdx.x == 0) {
        int zeros = 0;
        for (int k = 0; k < 128; ++k) zeros += (ei32[2 * k + 1] == 0);
        g_is64 = (zeros > 64) ? 1 : 0;
    }
}

// ---------------------------------------------------------------------------
// K1: zero counters
// ---------------------------------------------------------------------------
__global__ void init_kernel() {
    int i = blockIdx.x * blockDim.x + threadIdx.x;
    if (i < N_NODES) { g_cnt[i] = 0; g_cur[i] = 0; }
}

// ---------------------------------------------------------------------------
// K2: edge load (dtype-adaptive) + int32 copies + in-degree count
// ---------------------------------------------------------------------------
__global__ void convert_count_kernel(const void* __restrict__ eiv) {
    int e = blockIdx.x * blockDim.x + threadIdx.x;
    if (e >= N_EDGES) return;
    int s, d;
    if (g_is64) {
        const long long* ei = (const long long*)eiv;
        s = (int)ei[e];
        d = (int)ei[e + N_EDGES];
    } else {
        const int* ei = (const int*)eiv;
        s = ei[e];
        d = ei[e + N_EDGES];
    }
    if ((unsigned)s >= N_NODES) s = 0;          // defensive clamp
    g_src32[e] = s;
    if ((unsigned)d < N_NODES) {
        g_dst32[e] = d;
        atomicAdd(&g_cnt[d], 1);
    } else {
        g_dst32[e] = -1;                        // defensive: drop edge
    }
}

// ---------------------------------------------------------------------------
// K3: single-block exclusive scan of g_cnt -> g_off  (100K elements)
// ---------------------------------------------------------------------------
#define SCAN_T 1024
#define SCAN_CHUNK ((N_NODES + SCAN_T - 1) / SCAN_T)   // 98

__global__ void __launch_bounds__(SCAN_T)
scan_kernel() {
    __shared__ int ssum[SCAN_T];
    int t = threadIdx.x;
    int lo = t * SCAN_CHUNK;
    int hi = min(lo + SCAN_CHUNK, N_NODES);
    if (hi < lo) hi = lo;

    int local = 0;
    for (int i = lo; i < hi; ++i) local += g_cnt[i];
    ssum[t] = local;
    __syncthreads();

    for (int off = 1; off < SCAN_T; off <<= 1) {
        int v = (t >= off) ? ssum[t - off] : 0;
        __syncthreads();
        ssum[t] += v;
        __syncthreads();
    }
    int running = ssum[t] - local;   // exclusive base for this thread
    for (int i = lo; i < hi; ++i) {
        g_off[i] = running;
        running += g_cnt[i];
    }
}

// ---------------------------------------------------------------------------
// K4: fused GEMM + scale:  g_feat[i] = rsqrt(cnt[i]+1) * (x[i] @ W)
//     4 rows/thread; W staged in smem as packed f32 pairs; fma.rn.f32x2.
// ---------------------------------------------------------------------------
__device__ __forceinline__ void ffma2(unsigned long long& d,
                                      unsigned long long a,
                                      unsigned long long b) {
    asm("fma.rn.f32x2 %0, %1, %2, %0;" : "+l"(d) : "l"(a), "l"(b));
}

__device__ __forceinline__ unsigned long long pack2(float lo, float hi) {
    unsigned long long r;
    asm("mov.b64 %0, {%1, %2};" : "=l"(r) : "f"(lo), "f"(hi));
    return r;
}

__global__ void __launch_bounds__(128)
gemm_scale_kernel(const float* __restrict__ x,
                  const float* __restrict__ W) {
    // W is [512][16] row-major: adjacent j pairs are contiguous -> load as u64.
    __shared__ unsigned long long Ws[IN_DIM * 8];   // 32 KB
    const unsigned long long* W2 = (const unsigned long long*)W;
    for (int i = threadIdx.x; i < IN_DIM * 8; i += blockDim.x) Ws[i] = W2[i];
    __syncthreads();

    int t = blockIdx.x * blockDim.x + threadIdx.x;
    int row0 = t * 4;
    if (row0 >= N_NODES) return;

    unsigned long long acc2[4][8];
#pragma unroll
    for (int r = 0; r < 4; ++r)
#pragma unroll
        for (int j = 0; j < 8; ++j) acc2[r][j] = 0ull;

    const float4* xp0 = (const float4*)(x + (size_t)(row0 + 0) * IN_DIM);
    const float4* xp1 = (const float4*)(x + (size_t)(row0 + 1) * IN_DIM);
    const float4* xp2 = (const float4*)(x + (size_t)(row0 + 2) * IN_DIM);
    const float4* xp3 = (const float4*)(x + (size_t)(row0 + 3) * IN_DIM);
    const float4* xp[4] = {xp0, xp1, xp2, xp3};

    for (int k8 = 0; k8 < IN_DIM / 8; ++k8) {
        float xv[4][8];
#pragma unroll
        for (int r = 0; r < 4; ++r) {
            float4 a = xp[r][2 * k8];
            float4 b = xp[r][2 * k8 + 1];
            xv[r][0] = a.x; xv[r][1] = a.y; xv[r][2] = a.z; xv[r][3] = a.w;
            xv[r][4] = b.x; xv[r][5] = b.y; xv[r][6] = b.z; xv[r][7] = b.w;
        }
#pragma unroll
        for (int kk = 0; kk < 8; ++kk) {
            unsigned long long w[8];
            int kbase = (k8 * 8 + kk) * 8;
#pragma unroll
            for (int j = 0; j < 8; ++j) w[j] = Ws[kbase + j];
#pragma unroll
            for (int r = 0; r < 4; ++r) {
                unsigned long long x2 = pack2(xv[r][kk], xv[r][kk]);
#pragma unroll
                for (int j = 0; j < 8; ++j) ffma2(acc2[r][j], x2, w[j]);
            }
        }
    }

#pragma unroll
    for (int r = 0; r < 4; ++r) {
        int row = row0 + r;
        float dinv = rsqrtf((float)(g_cnt[row] + 1));
        float vals[16];
#pragma unroll
        for (int j = 0; j < 8; ++j) {
            float2 p = *(float2*)&acc2[r][j];
            vals[2 * j]     = p.x * dinv;
            vals[2 * j + 1] = p.y * dinv;
        }
        float4* gp = (float4*)(g_feat + (size_t)row * OUT_DIM);
#pragma unroll
        for (int q = 0; q < 4; ++q)
            gp[q] = make_float4(vals[4 * q], vals[4 * q + 1],
                                vals[4 * q + 2], vals[4 * q + 3]);
    }
}

// ---------------------------------------------------------------------------
// K5: counting-sort scatter: group src ids by dst (bounds-guarded)
// ---------------------------------------------------------------------------
__global__ void sort_scatter_kernel() {
    int e = blockIdx.x * blockDim.x + threadIdx.x;
    if (e >= N_EDGES) return;
    int d = g_dst32[e];
    if ((unsigned)d >= N_NODES) return;         // defensive
    int p = g_off[d] + atomicAdd(&g_cur[d], 1);
    if ((unsigned)p < N_EDGES)                  // defensive
        g_sorted_src[p] = g_src32[e];
}

// ---------------------------------------------------------------------------
// K6: gather + self-loop + dinv + bias. One warp per node, 2 edges per iter
//     (16 lanes = one contiguous 64B g_feat row each).
// ---------------------------------------------------------------------------
__global__ void __launch_bounds__(256)
gather_kernel(const float* __restrict__ b, float* __restrict__ out) {
    int warp = (blockIdx.x * blockDim.x + threadIdx.x) >> 5;
    if (warp >= N_NODES) return;
    int lane = threadIdx.x & 31;
    int half = lane >> 4;        // 0 or 1: which edge of the pair
    int sub  = lane & 15;        // feature index

    int cnt   = g_cnt[warp];
    int start = g_off[warp];

    float acc = 0.0f;
    for (int j = half; j < cnt; j += 2) {
        int s = g_sorted_src[start + j];
        acc += g_feat[(size_t)s * OUT_DIM + sub];
    }
    acc += __shfl_down_sync(0xFFFFFFFFu, acc, 16);

    if (lane < 16) {
        float dinv = rsqrtf((float)(cnt + 1));
        float v = (acc + g_feat[(size_t)warp * OUT_DIM + lane]) * dinv
                  + __ldg(&b[lane]);
        out[(size_t)warp * OUT_DIM + lane] = v;
    }
}

// ---------------------------------------------------------------------------
extern "C" void kernel_launch(void* const* d_in, const int* in_sizes, int n_in,
                              void* d_out, int out_size) {
    const float* x  = (const float*)d_in[0];
    const void*  ei = d_in[1];                  // [2, E] int32 OR int64
    const float* W  = (const float*)d_in[2];
    const float* b  = (const float*)d_in[3];
    float* out = (float*)d_out;

    (void)in_sizes; (void)n_in; (void)out_size;

    detect_kernel<<<1, 32>>>((const int*)ei);
    init_kernel<<<(N_NODES + 255) / 256, 256>>>();
    convert_count_kernel<<<(N_EDGES + 255) / 256, 256>>>(ei);
    scan_kernel<<<1, SCAN_T>>>();
    {
        int threads = N_NODES / 4;              // 25000 threads, 4 rows each
        gemm_scale_kernel<<<(threads + 127) / 128, 128>>>(x, W);
    }
    sort_scatter_kernel<<<(N_EDGES + 255) / 256, 256>>>();
    gather_kernel<<<(N_NODES * 32 + 255) / 256, 256>>>(b, out);
}

// round 8
// speedup vs baseline: 1.4570x; 1.4570x over previous
#include <cuda_runtime.h>

#define N_NODES 100000
#define IN_DIM  512
#define OUT_DIM 16
#define N_EDGES 3200000

#define SB 1024                                   // scan block size
#define NBLK ((N_NODES + SB - 1) / SB)            // 98 scan blocks

// Scratch (allocation-free rule: __device__ globals).
__device__ int   g_is64;                  // 1 if edge_index buffer is int64
__device__ int   g_cnt[N_NODES];          // in-degree (edges only, no self loop)
__device__ int   g_cur[N_NODES];          // scatter cursors
__device__ int   g_off[N_NODES];          // exclusive prefix of g_cnt
__device__ int   g_blksum[NBLK];          // per-block totals
__device__ int   g_blkoff[NBLK];          // exclusive prefix of block totals
__device__ int   g_src32[N_EDGES];
__device__ int   g_dst32[N_EDGES];
__device__ int   g_sorted_src[N_EDGES];   // src ids grouped by dst
__device__ __align__(16) float g_feat[N_NODES * OUT_DIM]; // rsqrt(deg)*(x@W)

// ---------------------------------------------------------------------------
// K0: dtype detection (int64 ids have zero high words at odd int32 slots)
// ---------------------------------------------------------------------------
__global__ void detect_kernel(const int* __restrict__ ei32) {
    if (threadIdx.x == 0 && blockIdx.x == 0) {
        int zeros = 0;
        for (int k = 0; k < 128; ++k) zeros += (ei32[2 * k + 1] == 0);
        g_is64 = (zeros > 64) ? 1 : 0;
    }
}

// ---------------------------------------------------------------------------
// K1: zero counters
// ---------------------------------------------------------------------------
__global__ void init_kernel() {
    int i = blockIdx.x * blockDim.x + threadIdx.x;
    if (i < N_NODES) { g_cnt[i] = 0; g_cur[i] = 0; }
}

// ---------------------------------------------------------------------------
// K2: edge load (dtype-adaptive) + int32 copies + in-degree count
// ---------------------------------------------------------------------------
__global__ void convert_count_kernel(const void* __restrict__ eiv) {
    int e = blockIdx.x * blockDim.x + threadIdx.x;
    if (e >= N_EDGES) return;
    int s, d;
    if (g_is64) {
        const long long* ei = (const long long*)eiv;
        s = (int)ei[e];
        d = (int)ei[e + N_EDGES];
    } else {
        const int* ei = (const int*)eiv;
        s = ei[e];
        d = ei[e + N_EDGES];
    }
    if ((unsigned)s >= N_NODES) s = 0;          // defensive clamp
    g_src32[e] = s;
    if ((unsigned)d < N_NODES) {
        g_dst32[e] = d;
        atomicAdd(&g_cnt[d], 1);
    } else {
        g_dst32[e] = -1;                        // defensive: drop edge
    }
}

// ---------------------------------------------------------------------------
// K3a: per-block scan (1024-chunk, smem Hillis-Steele), local-exclusive out
// ---------------------------------------------------------------------------
__global__ void __launch_bounds__(SB)
scan1_kernel() {
    __shared__ int s[SB];
    int t = threadIdx.x;
    int i = blockIdx.x * SB + t;
    int v = (i < N_NODES) ? g_cnt[i] : 0;
    s[t] = v;
    __syncthreads();
#pragma unroll
    for (int off = 1; off < SB; off <<= 1) {
        int u = (t >= off) ? s[t - off] : 0;
        __syncthreads();
        s[t] += u;
        __syncthreads();
    }
    if (i < N_NODES) g_off[i] = s[t] - v;       // local exclusive
    if (t == SB - 1) g_blksum[blockIdx.x] = s[t];
}

// ---------------------------------------------------------------------------
// K3b: scan the 98 block totals (one warp-ish block, smem serial is fine)
// ---------------------------------------------------------------------------
__global__ void __launch_bounds__(128)
scan2_kernel() {
    __shared__ int s[NBLK];
    int t = threadIdx.x;
    if (t < NBLK) s[t] = g_blksum[t];
    __syncthreads();
    if (t == 0) {
        int run = 0;
        for (int k = 0; k < NBLK; ++k) { int c = s[k]; s[k] = run; run += c; }
    }
    __syncthreads();
    if (t < NBLK) g_blkoff[t] = s[t];
}

// ---------------------------------------------------------------------------
// K3c: add block base offsets
// ---------------------------------------------------------------------------
__global__ void __launch_bounds__(SB)
scan3_kernel() {
    int i = blockIdx.x * SB + threadIdx.x;
    if (i < N_NODES) g_off[i] += g_blkoff[blockIdx.x];
}

// ---------------------------------------------------------------------------
// K4: fused GEMM + scale:  g_feat[i] = rsqrt(cnt[i]+1) * (x[i] @ W)
//     4 rows/thread; W staged in smem as packed f32 pairs; fma.rn.f32x2.
// ---------------------------------------------------------------------------
__device__ __forceinline__ void ffma2(unsigned long long& d,
                                      unsigned long long a,
                                      unsigned long long b) {
    asm("fma.rn.f32x2 %0, %1, %2, %0;" : "+l"(d) : "l"(a), "l"(b));
}

__device__ __forceinline__ unsigned long long pack2(float lo, float hi) {
    unsigned long long r;
    asm("mov.b64 %0, {%1, %2};" : "=l"(r) : "f"(lo), "f"(hi));
    return r;
}

__global__ void __launch_bounds__(128)
gemm_scale_kernel(const float* __restrict__ x,
                  const float* __restrict__ W) {
    __shared__ unsigned long long Ws[IN_DIM * 8];   // 32 KB
    const unsigned long long* W2 = (const unsigned long long*)W;
    for (int i = threadIdx.x; i < IN_DIM * 8; i += blockDim.x) Ws[i] = W2[i];
    __syncthreads();

    int t = blockIdx.x * blockDim.x + threadIdx.x;
    int row0 = t * 4;
    if (row0 >= N_NODES) return;

    unsigned long long acc2[4][8];
#pragma unroll
    for (int r = 0; r < 4; ++r)
#pragma unroll
        for (int j = 0; j < 8; ++j) acc2[r][j] = 0ull;

    const float4* xp0 = (const float4*)(x + (size_t)(row0 + 0) * IN_DIM);
    const float4* xp1 = (const float4*)(x + (size_t)(row0 + 1) * IN_DIM);
    const float4* xp2 = (const float4*)(x + (size_t)(row0 + 2) * IN_DIM);
    const float4* xp3 = (const float4*)(x + (size_t)(row0 + 3) * IN_DIM);
    const float4* xp[4] = {xp0, xp1, xp2, xp3};

    for (int k8 = 0; k8 < IN_DIM / 8; ++k8) {
        float xv[4][8];
#pragma unroll
        for (int r = 0; r < 4; ++r) {
            float4 a = xp[r][2 * k8];
            float4 b = xp[r][2 * k8 + 1];
            xv[r][0] = a.x; xv[r][1] = a.y; xv[r][2] = a.z; xv[r][3] = a.w;
            xv[r][4] = b.x; xv[r][5] = b.y; xv[r][6] = b.z; xv[r][7] = b.w;
        }
#pragma unroll
        for (int kk = 0; kk < 8; ++kk) {
            unsigned long long w[8];
            int kbase = (k8 * 8 + kk) * 8;
#pragma unroll
            for (int j = 0; j < 8; ++j) w[j] = Ws[kbase + j];
#pragma unroll
            for (int r = 0; r < 4; ++r) {
                unsigned long long x2 = pack2(xv[r][kk], xv[r][kk]);
#pragma unroll
                for (int j = 0; j < 8; ++j) ffma2(acc2[r][j], x2, w[j]);
            }
        }
    }

#pragma unroll
    for (int r = 0; r < 4; ++r) {
        int row = row0 + r;
        float dinv = rsqrtf((float)(g_cnt[row] + 1));
        float vals[16];
#pragma unroll
        for (int j = 0; j < 8; ++j) {
            float2 p = *(float2*)&acc2[r][j];
            vals[2 * j]     = p.x * dinv;
            vals[2 * j + 1] = p.y * dinv;
        }
        float4* gp = (float4*)(g_feat + (size_t)row * OUT_DIM);
#pragma unroll
        for (int q = 0; q < 4; ++q)
            gp[q] = make_float4(vals[4 * q], vals[4 * q + 1],
                                vals[4 * q + 2], vals[4 * q + 3]);
    }
}

// ---------------------------------------------------------------------------
// K5: counting-sort scatter: group src ids by dst (bounds-guarded)
// ---------------------------------------------------------------------------
__global__ void sort_scatter_kernel() {
    int e = blockIdx.x * blockDim.x + threadIdx.x;
    if (e >= N_EDGES) return;
    int d = g_dst32[e];
    if ((unsigned)d >= N_NODES) return;         // defensive
    int p = g_off[d] + atomicAdd(&g_cur[d], 1);
    if ((unsigned)p < N_EDGES)                  // defensive
        g_sorted_src[p] = g_src32[e];
}

// ---------------------------------------------------------------------------
// K6: gather + self-loop + dinv + bias. One warp per node, 2 edges per iter
//     (16 lanes = one contiguous 64B g_feat row each).
// ---------------------------------------------------------------------------
__global__ void __launch_bounds__(256)
gather_kernel(const float* __restrict__ b, float* __restrict__ out) {
    int warp = (blockIdx.x * blockDim.x + threadIdx.x) >> 5;
    if (warp >= N_NODES) return;
    int lane = threadIdx.x & 31;
    int half = lane >> 4;        // 0 or 1: which edge of the pair
    int sub  = lane & 15;        // feature index

    int cnt   = g_cnt[warp];
    int start = g_off[warp];

    float acc = 0.0f;
    for (int j = half; j < cnt; j += 2) {
        int s = g_sorted_src[start + j];
        acc += g_feat[(size_t)s * OUT_DIM + sub];
    }
    acc += __shfl_down_sync(0xFFFFFFFFu, acc, 16);

    if (lane < 16) {
        float dinv = rsqrtf((float)(cnt + 1));
        float v = (acc + g_feat[(size_t)warp * OUT_DIM + lane]) * dinv
                  + __ldg(&b[lane]);
        out[(size_t)warp * OUT_DIM + lane] = v;
    }
}

// ---------------------------------------------------------------------------
extern "C" void kernel_launch(void* const* d_in, const int* in_sizes, int n_in,
                              void* d_out, int out_size) {
    const float* x  = (const float*)d_in[0];
    const void*  ei = d_in[1];                  // [2, E] int32 OR int64
    const float* W  = (const float*)d_in[2];
    const float* b  = (const float*)d_in[3];
    float* out = (float*)d_out;

    (void)in_sizes; (void)n_in; (void)out_size;

    detect_kernel<<<1, 32>>>((const int*)ei);
    init_kernel<<<(N_NODES + 255) / 256, 256>>>();
    convert_count_kernel<<<(N_EDGES + 255) / 256, 256>>>(ei);
    scan1_kernel<<<NBLK, SB>>>();
    scan2_kernel<<<1, 128>>>();
    scan3_kernel<<<NBLK, SB>>>();
    {
        int threads = N_NODES / 4;              // 25000 threads, 4 rows each
        gemm_scale_kernel<<<(threads + 127) / 128, 128>>>(x, W);
    }
    sort_scatter_kernel<<<(N_EDGES + 255) / 256, 256>>>();
    gather_kernel<<<(N_NODES * 32 + 255) / 256, 256>>>(b, out);
}